// round 3
// baseline (speedup 1.0000x reference)
#include <cuda_runtime.h>
#include <math.h>

#define NODES 100000
#define NEDGES 3200000
#define INC 512
#define HIDC 256
#define OUTC 16
#define KITER 10

// ---------------- scratch (static device globals; no allocation) ----------------
__device__ __align__(16) float g_h0[NODES * OUTC];
__device__ __align__(16) float g_hA[NODES * OUTC];
__device__ __align__(16) float g_hB[NODES * OUTC];
__device__ __align__(16) float g_agg[NODES * OUTC];
__device__ float g_dinv[NODES];
__device__ int   g_deg[NODES];
__device__ int   g_src[NEDGES];
__device__ int   g_dst[NEDGES];
__device__ float g_norm[NEDGES];
__device__ int   g_is64;

// vector fp32 reduction to global (PTX ISA 8.1+, sm_90+) — 1 op per 16B
__device__ __forceinline__ void red_add_f4(float* addr, float4 v) {
    asm volatile("red.global.add.v4.f32 [%0], {%1, %2, %3, %4};"
                 :: "l"(addr), "f"(v.x), "f"(v.y), "f"(v.z), "f"(v.w)
                 : "memory");
}

__device__ __forceinline__ const float* sel_in(int s) {
    return s == 0 ? g_h0 : (s == 1 ? g_hA : g_hB);
}
__device__ __forceinline__ float* sel_out(int s) {
    return s == 1 ? g_hA : g_hB;
}

// ---------------- dtype detection for edge_index (int32 vs int64) ----------------
// If the buffer holds int64 values in [0, NODES), every odd int32 word (the high
// half, little-endian) is 0. If it holds int32 random node ids, the odd words are
// src[1], src[3], ... — random in [0,100000): all-64-zero probability ~1e-320.
__global__ void detect_kernel(const int* __restrict__ ei32) {
    if (threadIdx.x == 0 && blockIdx.x == 0) {
        int s = 0;
#pragma unroll
        for (int i = 0; i < 64; i++) s |= ei32[2 * i + 1];
        g_is64 = (s == 0) ? 1 : 0;
    }
}

// ---------------- init ----------------
__global__ void zero_kernel() {
    int i = blockIdx.x * blockDim.x + threadIdx.x;
    if (i < NODES * OUTC) { g_h0[i] = 0.f; g_agg[i] = 0.f; }
    if (i < NODES) g_deg[i] = 0;
}

// ---------------- fused MLP: h0 = relu(x@W1+b1)@W2 + b2 ----------------
// BM=128, BN=64 (hidden cols), BK=16; 256 threads; 8x4 register tile.
// Second layer fused in epilogue: partial [128x16] accumulated into g_h0 via red.v4.
#define BM 128
#define BN 64
#define BKK 16

__global__ __launch_bounds__(256) void mlp_kernel(
    const float* __restrict__ x, const float* __restrict__ W1,
    const float* __restrict__ b1, const float* __restrict__ W2,
    const float* __restrict__ b2)
{
    __shared__ __align__(16) float sm[9344];  // max(As+Bs = 3072, tile+W2s = 9344)
    float* As = sm;                      // [BKK][BM]
    float* Bs = sm + BKK * BM;           // [BKK][BN]

    const int tid = threadIdx.x;
    const int bm = blockIdx.x * BM;
    const int bn = blockIdx.y * BN;
    const int tr = tid >> 4;             // 0..15
    const int tc = tid & 15;             // 0..15

    float acc[8][4];
#pragma unroll
    for (int i = 0; i < 8; i++)
#pragma unroll
        for (int j = 0; j < 4; j++) acc[i][j] = 0.f;

    for (int k0 = 0; k0 < INC; k0 += BKK) {
        // x tile -> As (transposed): 512 float4 loads by 256 threads (2 each)
#pragma unroll
        for (int it = 0; it < 2; it++) {
            int l = tid + it * 256;
            int r = l >> 2;
            int kk = (l & 3) * 4;
            int gm = bm + r;
            float4 xa = make_float4(0.f, 0.f, 0.f, 0.f);
            if (gm < NODES) xa = *(const float4*)(x + (size_t)gm * INC + k0 + kk);
            As[(kk + 0) * BM + r] = xa.x;
            As[(kk + 1) * BM + r] = xa.y;
            As[(kk + 2) * BM + r] = xa.z;
            As[(kk + 3) * BM + r] = xa.w;
        }
        // W1 tile -> Bs: 256 float4 loads (1 each)
        {
            int kb = tid >> 4;
            int nn = (tid & 15) * 4;
            float4 wb = *(const float4*)(W1 + (size_t)(k0 + kb) * HIDC + bn + nn);
            *(float4*)(Bs + kb * BN + nn) = wb;
        }
        __syncthreads();
#pragma unroll
        for (int k = 0; k < BKK; k++) {
            float4 a0 = *(float4*)(As + k * BM + tr * 8);
            float4 a1 = *(float4*)(As + k * BM + tr * 8 + 4);
            float4 bv = *(float4*)(Bs + k * BN + tc * 4);
            float av[8] = {a0.x, a0.y, a0.z, a0.w, a1.x, a1.y, a1.z, a1.w};
            float bw[4] = {bv.x, bv.y, bv.z, bv.w};
#pragma unroll
            for (int i = 0; i < 8; i++)
#pragma unroll
                for (int j = 0; j < 4; j++)
                    acc[i][j] += av[i] * bw[j];
        }
        __syncthreads();
    }

    // epilogue: relu(acc + b1) -> smem tile [128][65] (padded, conflict-free)
    float bias[4];
#pragma unroll
    for (int j = 0; j < 4; j++) bias[j] = b1[bn + tc * 4 + j];

    float* tile = sm;                 // [BM][65] = 8320 floats
    float* W2s  = sm + BM * 65;       // [BN][OUTC] = 1024 floats

#pragma unroll
    for (int i = 0; i < 8; i++) {
        int m = tr * 8 + i;
#pragma unroll
        for (int j = 0; j < 4; j++) {
            float v = acc[i][j] + bias[j];
            tile[m * 65 + tc * 4 + j] = v > 0.f ? v : 0.f;
        }
    }
    // W2 slice [bn:bn+64, 0:16] -> smem
    {
        int rr = tid >> 2;
        int cc = (tid & 3) * 4;
        *(float4*)(W2s + rr * OUTC + cc) =
            *(const float4*)(W2 + (size_t)(bn + rr) * OUTC + cc);
    }
    __syncthreads();

    // second layer: each thread computes 8 outputs of one row
    int m2 = tid >> 1;
    int ch = (tid & 1) * 8;
    float acc2[8];
#pragma unroll
    for (int c = 0; c < 8; c++) acc2[c] = (blockIdx.y == 0) ? b2[ch + c] : 0.f;
#pragma unroll 8
    for (int k = 0; k < BN; k++) {
        float v = tile[m2 * 65 + k];
        float4 w0 = *(float4*)(W2s + k * OUTC + ch);
        float4 w1 = *(float4*)(W2s + k * OUTC + ch + 4);
        acc2[0] += v * w0.x; acc2[1] += v * w0.y;
        acc2[2] += v * w0.z; acc2[3] += v * w0.w;
        acc2[4] += v * w1.x; acc2[5] += v * w1.y;
        acc2[6] += v * w1.z; acc2[7] += v * w1.w;
    }
    int gm2 = bm + m2;
    if (gm2 < NODES) {
        red_add_f4(g_h0 + (size_t)gm2 * OUTC + ch,
                   make_float4(acc2[0], acc2[1], acc2[2], acc2[3]));
        red_add_f4(g_h0 + (size_t)gm2 * OUTC + ch + 4,
                   make_float4(acc2[4], acc2[5], acc2[6], acc2[7]));
    }
}

// ---------------- edge prep (dtype-agnostic via g_is64) ----------------
__global__ void edge_kernel(const void* __restrict__ ei) {
    int e = blockIdx.x * blockDim.x + threadIdx.x;
    if (e >= NEDGES) return;
    int s, d;
    if (g_is64) {
        const long long* p = (const long long*)ei;
        s = (int)p[e];
        d = (int)p[NEDGES + e];
    } else {
        const int* p = (const int*)ei;
        s = p[e];
        d = p[NEDGES + e];
    }
    g_src[e] = s;
    g_dst[e] = d;
    atomicAdd(&g_deg[d], 1);
}

__global__ void dinv_kernel() {
    int i = blockIdx.x * blockDim.x + threadIdx.x;
    if (i >= NODES) return;
    g_dinv[i] = rsqrtf((float)g_deg[i] + 1.0f);   // +1 = self loop
}

__global__ void norm_kernel() {
    int e = blockIdx.x * blockDim.x + threadIdx.x;
    if (e >= NEDGES) return;
    g_norm[e] = g_dinv[g_src[e]] * g_dinv[g_dst[e]];
}

// ---------------- propagation ----------------
// one thread per (edge, quad-of-4-channels): gather h[src], scale, red.v4 into agg[dst]
__global__ void scatter_kernel(int sel) {
    int t = blockIdx.x * blockDim.x + threadIdx.x;
    if (t >= NEDGES * 4) return;
    int e = t >> 2;
    int q = t & 3;
    const float* hin = sel_in(sel);
    float nrm = g_norm[e];
    int s = g_src[e];
    int d = g_dst[e];
    float4 v = *(const float4*)(hin + (size_t)s * OUTC + q * 4);
    red_add_f4(g_agg + (size_t)d * OUTC + q * 4,
               make_float4(nrm * v.x, nrm * v.y, nrm * v.z, nrm * v.w));
}

// h_out = 0.9*(agg + dinv^2 * h_in) + 0.1*h0 ; also re-zero agg for next iter
__global__ void combine_kernel(int sin, int sout) {
    int qd = blockIdx.x * blockDim.x + threadIdx.x;
    if (qd >= NODES * 4) return;
    int i = qd >> 2;
    const float* hin = sel_in(sin);
    float* hout = sel_out(sout);
    float di = g_dinv[i];
    float sn = di * di;
    float4 a  = *(float4*)(g_agg + (size_t)qd * 4);
    float4 hv = *(const float4*)(hin + (size_t)qd * 4);
    float4 h0v = *(const float4*)(g_h0 + (size_t)qd * 4);
    float4 o;
    o.x = 0.9f * (a.x + sn * hv.x) + 0.1f * h0v.x;
    o.y = 0.9f * (a.y + sn * hv.y) + 0.1f * h0v.y;
    o.z = 0.9f * (a.z + sn * hv.z) + 0.1f * h0v.z;
    o.w = 0.9f * (a.w + sn * hv.w) + 0.1f * h0v.w;
    *(float4*)(hout + (size_t)qd * 4) = o;
    *(float4*)(g_agg + (size_t)qd * 4) = make_float4(0.f, 0.f, 0.f, 0.f);
}

// ---------------- log_softmax over 16 classes ----------------
__global__ void lsm_kernel(int sel, float* __restrict__ out) {
    int i = blockIdx.x * blockDim.x + threadIdx.x;
    if (i >= NODES) return;
    const float* hin = sel_in(sel);
    const float4* p = (const float4*)(hin + (size_t)i * OUTC);
    float4 r0 = p[0], r1 = p[1], r2 = p[2], r3 = p[3];
    float v[16] = {r0.x, r0.y, r0.z, r0.w, r1.x, r1.y, r1.z, r1.w,
                   r2.x, r2.y, r2.z, r2.w, r3.x, r3.y, r3.z, r3.w};
    float m = v[0];
#pragma unroll
    for (int c = 1; c < 16; c++) m = fmaxf(m, v[c]);
    float ssum = 0.f;
#pragma unroll
    for (int c = 0; c < 16; c++) ssum += expf(v[c] - m);
    float ls = logf(ssum) + m;
    float4* o = (float4*)(out + (size_t)i * OUTC);
    o[0] = make_float4(v[0] - ls, v[1] - ls, v[2] - ls, v[3] - ls);
    o[1] = make_float4(v[4] - ls, v[5] - ls, v[6] - ls, v[7] - ls);
    o[2] = make_float4(v[8] - ls, v[9] - ls, v[10] - ls, v[11] - ls);
    o[3] = make_float4(v[12] - ls, v[13] - ls, v[14] - ls, v[15] - ls);
}

// ---------------- launch ----------------
extern "C" void kernel_launch(void* const* d_in, const int* in_sizes, int n_in,
                              void* d_out, int out_size)
{
    const float* x  = (const float*)d_in[0];
    const void* ei  = d_in[1];
    const float* W1 = (const float*)d_in[2];
    const float* b1 = (const float*)d_in[3];
    const float* W2 = (const float*)d_in[4];
    const float* b2 = (const float*)d_in[5];
    float* out      = (float*)d_out;

    detect_kernel<<<1, 32>>>((const int*)ei);
    zero_kernel<<<(NODES * OUTC + 255) / 256, 256>>>();
    mlp_kernel<<<dim3((NODES + BM - 1) / BM, HIDC / BN), 256>>>(x, W1, b1, W2, b2);
    edge_kernel<<<(NEDGES + 255) / 256, 256>>>(ei);
    dinv_kernel<<<(NODES + 255) / 256, 256>>>();
    norm_kernel<<<(NEDGES + 255) / 256, 256>>>();

    int cur = 0;
    for (int t = 0; t < KITER; t++) {
        scatter_kernel<<<(NEDGES * 4 + 255) / 256, 256>>>(cur);
        int nxt = (cur == 1) ? 2 : 1;
        combine_kernel<<<(NODES * 4 + 255) / 256, 256>>>(cur, nxt);
        cur = nxt;
    }
    lsm_kernel<<<(NODES + 255) / 256, 256>>>(cur, out);
}

// round 5
// speedup vs baseline: 1.2178x; 1.2178x over previous
#include <cuda_runtime.h>
#include <math.h>

#define NODES 100000
#define NEDGES 3200000
#define INC 512
#define HIDC 256
#define OUTC 16
#define KITER 10

// ---------------- scratch (static device globals; no allocation) ----------------
__device__ __align__(16) float g_h0[NODES * OUTC];
__device__ __align__(16) float g_hA[NODES * OUTC];
__device__ __align__(16) float g_hB[NODES * OUTC];
__device__ __align__(16) float g_agg[NODES * OUTC];
__device__ float g_dinv[NODES];
__device__ int   g_deg[NODES];
__device__ int   g_src[NEDGES];
__device__ int   g_dst[NEDGES];
__device__ float g_norm[NEDGES];
__device__ int   g_is64;

// vector fp32 reduction to global (PTX ISA 8.1+, sm_90+)
__device__ __forceinline__ void red_add_f4(float* addr, float4 v) {
    asm volatile("red.global.add.v4.f32 [%0], {%1, %2, %3, %4};"
                 :: "l"(addr), "f"(v.x), "f"(v.y), "f"(v.z), "f"(v.w)
                 : "memory");
}

__device__ __forceinline__ unsigned tf32_of(float v) {
    unsigned r;
    asm("cvt.rna.tf32.f32 %0, %1;" : "=r"(r) : "f"(v));
    return r;
}

__device__ __forceinline__ const float* sel_in(int s) {
    return s == 0 ? g_h0 : (s == 1 ? g_hA : g_hB);
}
__device__ __forceinline__ float* sel_out(int s) {
    return s == 1 ? g_hA : g_hB;
}

// ---------------- dtype detection for edge_index (int32 vs int64) ----------------
__global__ void detect_kernel(const int* __restrict__ ei32) {
    if (threadIdx.x == 0 && blockIdx.x == 0) {
        int s = 0;
#pragma unroll
        for (int i = 0; i < 64; i++) s |= ei32[2 * i + 1];
        g_is64 = (s == 0) ? 1 : 0;
    }
}

// ---------------- init ----------------
__global__ void zero_kernel() {
    int i = blockIdx.x * blockDim.x + threadIdx.x;
    if (i < NODES * OUTC) { g_h0[i] = 0.f; g_agg[i] = 0.f; }
    if (i < NODES) g_deg[i] = 0;
}

// ---------------- fused MLP via tf32 tensor cores ----------------
// h0 = relu(x@W1+b1)@W2 + b2
// BM=128, BN=64 (hidden cols), BK=32; 256 threads = 8 warps in 4(m)x2(n) grid;
// each warp computes a 32x32 tile with mma.sync.m16n8k8 tf32 (2x4 fragments).
// Layer 2 fused in epilogue (fp32), accumulated into g_h0 via red.v4.
#define BM 128
#define BN 64
#define BKK 32
#define XS_STRIDE 136   // 128 + 8 pad -> conflict-free frag loads
#define WS_STRIDE 72    // 64 + 8 pad

__global__ __launch_bounds__(256) void mlp_tc_kernel(
    const float* __restrict__ x, const float* __restrict__ W1,
    const float* __restrict__ b1, const float* __restrict__ W2,
    const float* __restrict__ b2)
{
    // phase 1 needs 32*136 + 32*72 = 6656 floats; epilogue needs 128*65+64*16 = 9344
    __shared__ __align__(16) float sm[9344];
    float* Xt = sm;                       // [BKK][XS_STRIDE]  (k-major, transposed X)
    float* Ws = sm + BKK * XS_STRIDE;     // [BKK][WS_STRIDE]

    const int tid  = threadIdx.x;
    const int lane = tid & 31;
    const int wid  = tid >> 5;
    const int warp_m = wid >> 1;          // 0..3
    const int warp_n = wid & 1;           // 0..1
    const int bm = blockIdx.x * BM;
    const int bn = blockIdx.y * BN;
    const int gID = lane >> 2;            // 0..7
    const int tig = lane & 3;             // 0..3

    float acc[2][4][4];
#pragma unroll
    for (int mt = 0; mt < 2; mt++)
#pragma unroll
        for (int nt = 0; nt < 4; nt++)
#pragma unroll
            for (int v = 0; v < 4; v++) acc[mt][nt][v] = 0.f;

    for (int k0 = 0; k0 < INC; k0 += BKK) {
        // X tile -> Xt transposed: 1024 float4 loads by 256 threads (4 each)
#pragma unroll
        for (int it = 0; it < 4; it++) {
            int l  = tid + it * 256;
            int r  = l & 127;             // row within tile
            int kq = l >> 7;              // 0..7, quad of k
            int gm = bm + r;
            float4 v = make_float4(0.f, 0.f, 0.f, 0.f);
            if (gm < NODES) v = *(const float4*)(x + (size_t)gm * INC + k0 + kq * 4);
            ((unsigned*)Xt)[(kq * 4 + 0) * XS_STRIDE + r] = tf32_of(v.x);
            ((unsigned*)Xt)[(kq * 4 + 1) * XS_STRIDE + r] = tf32_of(v.y);
            ((unsigned*)Xt)[(kq * 4 + 2) * XS_STRIDE + r] = tf32_of(v.z);
            ((unsigned*)Xt)[(kq * 4 + 3) * XS_STRIDE + r] = tf32_of(v.w);
        }
        // W1 tile -> Ws: 512 float4 loads (2 each)
#pragma unroll
        for (int it = 0; it < 2; it++) {
            int l  = tid + it * 256;
            int kr = l >> 4;              // 0..31
            int nq = l & 15;              // quad of n
            float4 w = *(const float4*)(W1 + (size_t)(k0 + kr) * HIDC + bn + nq * 4);
            uint4 t;
            t.x = tf32_of(w.x); t.y = tf32_of(w.y);
            t.z = tf32_of(w.z); t.w = tf32_of(w.w);
            *(uint4*)((unsigned*)Ws + kr * WS_STRIDE + nq * 4) = t;
        }
        __syncthreads();

#pragma unroll
        for (int ks = 0; ks < 4; ks++) {
            const int kb = ks * 8;
            unsigned a[2][4], b[4][2];
#pragma unroll
            for (int mt = 0; mt < 2; mt++) {
                int m = warp_m * 32 + mt * 16 + gID;
                const unsigned* X32 = (const unsigned*)Xt;
                a[mt][0] = X32[(kb + tig) * XS_STRIDE + m];
                a[mt][1] = X32[(kb + tig) * XS_STRIDE + m + 8];
                a[mt][2] = X32[(kb + tig + 4) * XS_STRIDE + m];
                a[mt][3] = X32[(kb + tig + 4) * XS_STRIDE + m + 8];
            }
#pragma unroll
            for (int nt = 0; nt < 4; nt++) {
                int n = warp_n * 32 + nt * 8 + gID;
                const unsigned* W32 = (const unsigned*)Ws;
                b[nt][0] = W32[(kb + tig) * WS_STRIDE + n];
                b[nt][1] = W32[(kb + tig + 4) * WS_STRIDE + n];
            }
#pragma unroll
            for (int mt = 0; mt < 2; mt++)
#pragma unroll
                for (int nt = 0; nt < 4; nt++) {
                    float* c = acc[mt][nt];
                    asm volatile(
                        "mma.sync.aligned.m16n8k8.row.col.f32.tf32.tf32.f32 "
                        "{%0,%1,%2,%3}, {%4,%5,%6,%7}, {%8,%9}, {%0,%1,%2,%3};"
                        : "+f"(c[0]), "+f"(c[1]), "+f"(c[2]), "+f"(c[3])
                        : "r"(a[mt][0]), "r"(a[mt][1]), "r"(a[mt][2]), "r"(a[mt][3]),
                          "r"(b[nt][0]), "r"(b[nt][1]));
                }
        }
        __syncthreads();
    }

    // epilogue: bias + relu -> smem tile [128][65]
    float* tile = sm;                 // [BM][65] = 8320 floats
    float* W2s  = sm + BM * 65;       // [BN][OUTC] = 1024 floats

#pragma unroll
    for (int mt = 0; mt < 2; mt++) {
        int r0 = warp_m * 32 + mt * 16 + gID;
        int r1 = r0 + 8;
#pragma unroll
        for (int nt = 0; nt < 4; nt++) {
            int c0 = warp_n * 32 + nt * 8 + 2 * tig;
            int c1 = c0 + 1;
            float bc0 = b1[bn + c0];
            float bc1 = b1[bn + c1];
            float v00 = acc[mt][nt][0] + bc0;
            float v01 = acc[mt][nt][1] + bc1;
            float v10 = acc[mt][nt][2] + bc0;
            float v11 = acc[mt][nt][3] + bc1;
            tile[r0 * 65 + c0] = v00 > 0.f ? v00 : 0.f;
            tile[r0 * 65 + c1] = v01 > 0.f ? v01 : 0.f;
            tile[r1 * 65 + c0] = v10 > 0.f ? v10 : 0.f;
            tile[r1 * 65 + c1] = v11 > 0.f ? v11 : 0.f;
        }
    }
    // W2 slice [bn:bn+64, 0:16] -> smem
    {
        int rr = tid >> 2;
        int cc = (tid & 3) * 4;
        *(float4*)(W2s + rr * OUTC + cc) =
            *(const float4*)(W2 + (size_t)(bn + rr) * OUTC + cc);
    }
    __syncthreads();

    // second layer (fp32): each thread computes 8 outputs of one row
    int m2 = tid >> 1;
    int ch = (tid & 1) * 8;
    float acc2[8];
#pragma unroll
    for (int c = 0; c < 8; c++) acc2[c] = (blockIdx.y == 0) ? b2[ch + c] : 0.f;
#pragma unroll 8
    for (int k = 0; k < BN; k++) {
        float v = tile[m2 * 65 + k];
        float4 w0 = *(float4*)(W2s + k * OUTC + ch);
        float4 w1 = *(float4*)(W2s + k * OUTC + ch + 4);
        acc2[0] += v * w0.x; acc2[1] += v * w0.y;
        acc2[2] += v * w0.z; acc2[3] += v * w0.w;
        acc2[4] += v * w1.x; acc2[5] += v * w1.y;
        acc2[6] += v * w1.z; acc2[7] += v * w1.w;
    }
    int gm2 = bm + m2;
    if (gm2 < NODES) {
        red_add_f4(g_h0 + (size_t)gm2 * OUTC + ch,
                   make_float4(acc2[0], acc2[1], acc2[2], acc2[3]));
        red_add_f4(g_h0 + (size_t)gm2 * OUTC + ch + 4,
                   make_float4(acc2[4], acc2[5], acc2[6], acc2[7]));
    }
}

// ---------------- edge prep (dtype-agnostic via g_is64) ----------------
__global__ void edge_kernel(const void* __restrict__ ei) {
    int e = blockIdx.x * blockDim.x + threadIdx.x;
    if (e >= NEDGES) return;
    int s, d;
    if (g_is64) {
        const long long* p = (const long long*)ei;
        s = (int)p[e];
        d = (int)p[NEDGES + e];
    } else {
        const int* p = (const int*)ei;
        s = p[e];
        d = p[NEDGES + e];
    }
    g_src[e] = s;
    g_dst[e] = d;
    atomicAdd(&g_deg[d], 1);
}

__global__ void dinv_kernel() {
    int i = blockIdx.x * blockDim.x + threadIdx.x;
    if (i >= NODES) return;
    g_dinv[i] = rsqrtf((float)g_deg[i] + 1.0f);   // +1 = self loop
}

__global__ void norm_kernel() {
    int e = blockIdx.x * blockDim.x + threadIdx.x;
    if (e >= NEDGES) return;
    g_norm[e] = g_dinv[g_src[e]] * g_dinv[g_dst[e]];
}

// ---------------- propagation ----------------
__global__ void scatter_kernel(int sel) {
    int t = blockIdx.x * blockDim.x + threadIdx.x;
    if (t >= NEDGES * 4) return;
    int e = t >> 2;
    int q = t & 3;
    const float* hin = sel_in(sel);
    float nrm = g_norm[e];
    int s = g_src[e];
    int d = g_dst[e];
    float4 v = *(const float4*)(hin + (size_t)s * OUTC + q * 4);
    red_add_f4(g_agg + (size_t)d * OUTC + q * 4,
               make_float4(nrm * v.x, nrm * v.y, nrm * v.z, nrm * v.w));
}

// h_out = 0.9*(agg + dinv^2 * h_in) + 0.1*h0 ; also re-zero agg for next iter
__global__ void combine_kernel(int sin, int sout) {
    int qd = blockIdx.x * blockDim.x + threadIdx.x;
    if (qd >= NODES * 4) return;
    int i = qd >> 2;
    const float* hin = sel_in(sin);
    float* hout = sel_out(sout);
    float di = g_dinv[i];
    float sn = di * di;
    float4 a  = *(float4*)(g_agg + (size_t)qd * 4);
    float4 hv = *(const float4*)(hin + (size_t)qd * 4);
    float4 h0v = *(const float4*)(g_h0 + (size_t)qd * 4);
    float4 o;
    o.x = 0.9f * (a.x + sn * hv.x) + 0.1f * h0v.x;
    o.y = 0.9f * (a.y + sn * hv.y) + 0.1f * h0v.y;
    o.z = 0.9f * (a.z + sn * hv.z) + 0.1f * h0v.z;
    o.w = 0.9f * (a.w + sn * hv.w) + 0.1f * h0v.w;
    *(float4*)(hout + (size_t)qd * 4) = o;
    *(float4*)(g_agg + (size_t)qd * 4) = make_float4(0.f, 0.f, 0.f, 0.f);
}

// ---------------- log_softmax over 16 classes ----------------
__global__ void lsm_kernel(int sel, float* __restrict__ out) {
    int i = blockIdx.x * blockDim.x + threadIdx.x;
    if (i >= NODES) return;
    const float* hin = sel_in(sel);
    const float4* p = (const float4*)(hin + (size_t)i * OUTC);
    float4 r0 = p[0], r1 = p[1], r2 = p[2], r3 = p[3];
    float v[16] = {r0.x, r0.y, r0.z, r0.w, r1.x, r1.y, r1.z, r1.w,
                   r2.x, r2.y, r2.z, r2.w, r3.x, r3.y, r3.z, r3.w};
    float m = v[0];
#pragma unroll
    for (int c = 1; c < 16; c++) m = fmaxf(m, v[c]);
    float ssum = 0.f;
#pragma unroll
    for (int c = 0; c < 16; c++) ssum += expf(v[c] - m);
    float ls = logf(ssum) + m;
    float4* o = (float4*)(out + (size_t)i * OUTC);
    o[0] = make_float4(v[0] - ls, v[1] - ls, v[2] - ls, v[3] - ls);
    o[1] = make_float4(v[4] - ls, v[5] - ls, v[6] - ls, v[7] - ls);
    o[2] = make_float4(v[8] - ls, v[9] - ls, v[10] - ls, v[11] - ls);
    o[3] = make_float4(v[12] - ls, v[13] - ls, v[14] - ls, v[15] - ls);
}

// ---------------- launch ----------------
extern "C" void kernel_launch(void* const* d_in, const int* in_sizes, int n_in,
                              void* d_out, int out_size)
{
    const float* x  = (const float*)d_in[0];
    const void* ei  = d_in[1];
    const float* W1 = (const float*)d_in[2];
    const float* b1 = (const float*)d_in[3];
    const float* W2 = (const float*)d_in[4];
    const float* b2 = (const float*)d_in[5];
    float* out      = (float*)d_out;

    detect_kernel<<<1, 32>>>((const int*)ei);
    zero_kernel<<<(NODES * OUTC + 255) / 256, 256>>>();
    mlp_tc_kernel<<<dim3((NODES + BM - 1) / BM, HIDC / BN), 256>>>(x, W1, b1, W2, b2);
    edge_kernel<<<(NEDGES + 255) / 256, 256>>>(ei);
    dinv_kernel<<<(NODES + 255) / 256, 256>>>();
    norm_kernel<<<(NEDGES + 255) / 256, 256>>>();

    int cur = 0;
    for (int t = 0; t < KITER; t++) {
        scatter_kernel<<<(NEDGES * 4 + 255) / 256, 256>>>(cur);
        int nxt = (cur == 1) ? 2 : 1;
        combine_kernel<<<(NODES * 4 + 255) / 256, 256>>>(cur, nxt);
        cur = nxt;
    }
    lsm_kernel<<<(NODES + 255) / 256, 256>>>(cur, out);
}